// round 8
// baseline (speedup 1.0000x reference)
#include <cuda_runtime.h>

#define Nn 50000
#define Ee 640000
#define Hh 128
#define CHUNK 16

// device-global scratch (no allocs allowed)
__device__ float g_msg[Nn * Hh];
__device__ float g_hs[Nn * Hh];   // h @ We1[0:128]   + be1
__device__ float g_hd[Nn * Hh];   // h @ We1[128:256]

__device__ __forceinline__ float silu_f(float v) {
    return v / (1.f + __expf(-v));
}

union U64F2 { unsigned long long u; float2 f; };

// column owned by (tx, cp): cp 0,1 -> tx*4 + cp*2 ; cp 2,3 -> 64 + tx*4 + (cp-2)*2
__device__ __forceinline__ int colof(int tx, int cp) {
    return (cp < 2) ? (tx * 4 + cp * 2) : (64 + tx * 4 + (cp - 2) * 2);
}

__device__ __forceinline__ void cp_async16(float* dst, const float* src) {
    unsigned u = (unsigned)__cvta_generic_to_shared(dst);
    asm volatile("cp.async.ca.shared.global [%0], [%1], 16;" :: "r"(u), "l"(src));
}
__device__ __forceinline__ void cp_commit() { asm volatile("cp.async.commit_group;"); }
template<int P> __device__ __forceinline__ void cp_wait() {
    asm volatile("cp.async.wait_group %0;" :: "n"(P));
}

// stage one CHUNK x 128 fp32 slab of B into smem via cp.async (8 KB)
__device__ __forceinline__ void stage_b(float* dst, const float* __restrict__ src, int tid) {
#pragma unroll
    for (int s = 0; s < CHUNK / 4; s++) {
        int idx = tid + s * 128;
        int row = idx >> 5, col = (idx & 31) * 4;
        cp_async16(dst + row * 128 + col, src + row * 128 + col);
    }
}

// Register-blocked fused GEMM: C[64 x 128] += A[64 x K] * B[K x 128]
// A in SMEM (row stride AW, mult of 4), B double-buffered via cp.async.
// Thread (ty,tx) owns rows ty*8..+7, cols {tx*4..+3, 64+tx*4..+3} (conflict-free).
// Packed f32x2 accumulators (2x FFMA rate). K mult of CHUNK.
//
// One barrier per chunk, placed AFTER cp_wait (cp.async completion is
// per-thread; the barrier publishes chunk c across threads — the R5 bug was
// barring BEFORE the wait). The same barrier proves every warp finished
// compute(c-1), so restaging buffer (c+1)&1 right after it is safe, and the
// stage overlaps compute(c).
template <int AW, bool ZERO_INIT>
__device__ __forceinline__ void gemm_tile(
    const float* sA, float* sB, const float* __restrict__ Bg, int K,
    int ty, int tx, int tid, unsigned long long acc2[8][4])
{
    if (ZERO_INIT) {
#pragma unroll
        for (int r = 0; r < 8; r++)
#pragma unroll
            for (int cp = 0; cp < 4; cp++) acc2[r][cp] = 0ull;
    }

    const int nCh = K / CHUNK;

    stage_b(sB, Bg, tid);
    cp_commit();

    for (int c = 0; c < nCh; c++) {
        cp_wait<0>();      // own chunk-c copies complete (only pending group)
        __syncthreads();   // publish chunk c; all warps past compute(c-1)
        if (c + 1 < nCh) {
            stage_b(sB + ((c + 1) & 1) * (CHUNK * 128), Bg + (c + 1) * CHUNK * 128, tid);
            cp_commit();   // lands during compute(c)
        }

        const float* A  = sA + (ty * 8) * AW + c * CHUNK;
        const float* Bb = sB + (c & 1) * (CHUNK * 128);
#pragma unroll
        for (int kq = 0; kq < CHUNK / 4; kq++) {
            float4 a4[8];
#pragma unroll
            for (int r = 0; r < 8; r++)
                a4[r] = *(const float4*)(A + r * AW + kq * 4);
#pragma unroll
            for (int k2 = 0; k2 < 4; k2++) {
                const float* brow = Bb + (kq * 4 + k2) * 128;
                ulonglong2 t0 = *(const ulonglong2*)(brow + tx * 4);
                ulonglong2 t1 = *(const ulonglong2*)(brow + 64 + tx * 4);
                unsigned long long b2[4] = { t0.x, t0.y, t1.x, t1.y };
#pragma unroll
                for (int r = 0; r < 8; r++) {
                    float a = (k2 == 0) ? a4[r].x : (k2 == 1) ? a4[r].y
                             : (k2 == 2) ? a4[r].z : a4[r].w;
                    unsigned long long a2;
                    asm("mov.b64 %0, {%1, %1};" : "=l"(a2) : "f"(a));
#pragma unroll
                    for (int cp = 0; cp < 4; cp++)
                        asm("fma.rn.f32x2 %0, %1, %2, %0;"
                            : "+l"(acc2[r][cp]) : "l"(a2), "l"(b2[cp]));
                }
            }
        }
    }
    __syncthreads();   // all warps done reading sA before caller rewrites it
}

// bias + SiLU, write back into sA[.. 0..127] (two conflict-free STS.128 per row)
template <int AW>
__device__ __forceinline__ void bias_silu_store(
    unsigned long long acc2[8][4], const float* __restrict__ bias,
    float* sA, int ty, int tx)
{
#pragma unroll
    for (int r = 0; r < 8; r++) {
        float* row = sA + (ty * 8 + r) * AW;
        U64F2 u0, u1;
        u0.u = acc2[r][0]; u1.u = acc2[r][1];
        float4 v0;
        v0.x = silu_f(u0.f.x + bias[tx * 4 + 0]);
        v0.y = silu_f(u0.f.y + bias[tx * 4 + 1]);
        v0.z = silu_f(u1.f.x + bias[tx * 4 + 2]);
        v0.w = silu_f(u1.f.y + bias[tx * 4 + 3]);
        *(float4*)(row + tx * 4) = v0;
        u0.u = acc2[r][2]; u1.u = acc2[r][3];
        float4 v1;
        v1.x = silu_f(u0.f.x + bias[64 + tx * 4 + 0]);
        v1.y = silu_f(u0.f.y + bias[64 + tx * 4 + 1]);
        v1.z = silu_f(u1.f.x + bias[64 + tx * 4 + 2]);
        v1.w = silu_f(u1.f.y + bias[64 + tx * 4 + 3]);
        *(float4*)(row + 64 + tx * 4) = v1;
    }
}

// ---------------------------------------------------------------------------
__global__ void init_kernel(const float* __restrict__ x, float* __restrict__ xo) {
    int idx = blockIdx.x * 256 + threadIdx.x;
    if (idx < Nn * 3) xo[idx] = x[idx];
    if (idx < Nn * Hh) g_msg[idx] = 0.f;
}

// ---------------------------------------------------------------------------
// precompute: g_hs = h @ We1[0:128] + be1 ; g_hd = h @ We1[128:256]
__global__ __launch_bounds__(128, 4) void pre_kernel(
    const float* __restrict__ h, const float* __restrict__ We1,
    const float* __restrict__ be1)
{
    const int AW = 132;
    extern __shared__ float sm[];
    float* sA = sm;                  // 64*132
    float* sB = sm + 64 * AW;        // 2*CHUNK*128

    int tid = threadIdx.x;
    int ty = tid >> 4, tx = tid & 15;
    int n0 = blockIdx.x * 64;

    for (int idx = tid; idx < 64 * 32; idx += 128) {
        int i = idx >> 5, q = (idx & 31) * 4;
        int n = n0 + i;
        float4 v = make_float4(0.f, 0.f, 0.f, 0.f);
        if (n < Nn) v = *(const float4*)(h + (size_t)n * Hh + q);
        *(float4*)(sA + i * AW + q) = v;
    }

    unsigned long long acc2[8][4];

    gemm_tile<AW, true>(sA, sB, We1, Hh, ty, tx, tid, acc2);
#pragma unroll
    for (int r = 0; r < 8; r++) {
        int n = n0 + ty * 8 + r;
        if (n < Nn) {
#pragma unroll
            for (int cp = 0; cp < 4; cp++) {
                U64F2 u; u.u = acc2[r][cp];
                int f = colof(tx, cp);
                float2 o; o.x = u.f.x + be1[f]; o.y = u.f.y + be1[f + 1];
                *(float2*)(g_hs + (size_t)n * Hh + f) = o;
            }
        }
    }

    gemm_tile<AW, true>(sA, sB, We1 + 128 * Hh, Hh, ty, tx, tid, acc2);
#pragma unroll
    for (int r = 0; r < 8; r++) {
        int n = n0 + ty * 8 + r;
        if (n < Nn) {
#pragma unroll
            for (int cp = 0; cp < 4; cp++) {
                U64F2 u; u.u = acc2[r][cp];
                *(float2*)(g_hd + (size_t)n * Hh + colof(tx, cp)) = u.f;
            }
        }
    }
}

// ---------------------------------------------------------------------------
// edge kernel: layer1 via precomputed gathers; fused layer2 + coord MLP + scatters
__global__ __launch_bounds__(128, 4) void edge_kernel(
    const float* __restrict__ x, const int* __restrict__ ei,
    const float* __restrict__ We1,                      // row 256 = dist^2 weights
    const float* __restrict__ We2, const float* __restrict__ be2,
    const float* __restrict__ Wc1, const float* __restrict__ bc1,
    const float* __restrict__ Wc2, float* __restrict__ xo)
{
    const int AW = 132;
    extern __shared__ float sm[];
    float* sA   = sm;                          // 64*132
    float* sB   = sm + 64 * AW;                // 2*CHUNK*128 = 4096
    float* sRel = sB + 2 * CHUNK * 128;        // 192
    float* sD2  = sRel + 192;                  // 64
    float* sW   = sD2 + 64;                    // 128 (We1 row 256)
    int*   sSrc = (int*)(sW + 128);            // 64
    int*   sDst = sSrc + 64;                   // 64

    int tid = threadIdx.x;
    int ty = tid >> 4, tx = tid & 15;
    int e0 = blockIdx.x * 64;

    if (tid < 64) {
        int ge = e0 + tid;
        int s = ei[ge], d = ei[Ee + ge];
        float rx = x[s * 3 + 0] - x[d * 3 + 0];
        float ry = x[s * 3 + 1] - x[d * 3 + 1];
        float rz = x[s * 3 + 2] - x[d * 3 + 2];
        sRel[tid * 3 + 0] = rx; sRel[tid * 3 + 1] = ry; sRel[tid * 3 + 2] = rz;
        sD2[tid] = rx * rx + ry * ry + rz * rz;
        sSrc[tid] = s; sDst[tid] = d;
    } else if (tid < 96) {
        int t = tid - 64;
        *(float4*)(sW + t * 4) = *(const float4*)(We1 + 256 * Hh + t * 4);
    }
    __syncthreads();

    // layer-1 output directly: sA[i] = silu(hs[src] + hd[dst] + d2 * w256)
    for (int idx = tid; idx < 64 * 32; idx += 128) {
        int i = idx >> 5, q = (idx & 31) * 4;
        int s = sSrc[i], d = sDst[i];
        float d2 = sD2[i];
        float4 a = *(const float4*)(g_hs + (size_t)s * Hh + q);
        float4 b = *(const float4*)(g_hd + (size_t)d * Hh + q);
        float4 w = *(const float4*)(sW + q);
        float* p = sA + i * AW + q;
        p[0] = silu_f(a.x + b.x + d2 * w.x);
        p[1] = silu_f(a.y + b.y + d2 * w.y);
        p[2] = silu_f(a.z + b.z + d2 * w.z);
        p[3] = silu_f(a.w + b.w + d2 * w.w);
    }
    // (first barrier inside gemm_tile covers these writes)

    unsigned long long acc2[8][4];

    // layer 2: m_ij = silu([64x128] @ We2 + be2), left in sA
    gemm_tile<AW, true>(sA, sB, We2, Hh, ty, tx, tid, acc2);
    bias_silu_store<AW>(acc2, be2, sA, ty, tx);

    // coord MLP: w = silu(m_ij @ Wc1 + bc1) . Wc2
    gemm_tile<AW, true>(sA, sB, Wc1, Hh, ty, tx, tid, acc2);

    float partial[8];
#pragma unroll
    for (int r = 0; r < 8; r++) partial[r] = 0.f;
#pragma unroll
    for (int r = 0; r < 8; r++)
#pragma unroll
        for (int cp = 0; cp < 4; cp++) {
            U64F2 u; u.u = acc2[r][cp];
            int f = colof(tx, cp);
            partial[r] += silu_f(u.f.x + bc1[f])     * Wc2[f];
            partial[r] += silu_f(u.f.y + bc1[f + 1]) * Wc2[f + 1];
        }
#pragma unroll
    for (int off = 8; off > 0; off >>= 1)
#pragma unroll
        for (int r = 0; r < 8; r++)
            partial[r] += __shfl_xor_sync(0xffffffffu, partial[r], off);

    if (tx == 0) {
#pragma unroll
        for (int r = 0; r < 8; r++) {
            int i = ty * 8 + r;
            float w = partial[r];
            int d = sDst[i];
            atomicAdd(xo + (size_t)d * 3 + 0, sRel[i * 3 + 0] * w);
            atomicAdd(xo + (size_t)d * 3 + 1, sRel[i * 3 + 1] * w);
            atomicAdd(xo + (size_t)d * 3 + 2, sRel[i * 3 + 2] * w);
        }
    }

    // msg_agg scatter: m_ij still in sA; vectorized global reductions
    for (int idx = tid; idx < 64 * 32; idx += 128) {
        int i = idx >> 5, q = (idx & 31) * 4;
        const float* p = sA + i * AW + q;
        float v0 = p[0], v1 = p[1], v2 = p[2], v3 = p[3];
        float* gp = g_msg + (size_t)sDst[i] * Hh + q;
        asm volatile("red.global.add.v4.f32 [%0], {%1, %2, %3, %4};"
                     :: "l"(gp), "f"(v0), "f"(v1), "f"(v2), "f"(v3) : "memory");
    }
}

// ---------------------------------------------------------------------------
// node kernel: h_out = h + Wn2 @ SiLU(h@Wn1_top + msg@Wn1_bot + bn1) + bn2
__global__ __launch_bounds__(128, 4) void node_kernel(
    const float* __restrict__ h,
    const float* __restrict__ Wn1, const float* __restrict__ bn1,
    const float* __restrict__ Wn2, const float* __restrict__ bn2,
    float* __restrict__ ho)
{
    const int AW = 132;
    extern __shared__ float sm[];
    float* sA = sm;                 // 64 * 132
    float* sB = sm + 64 * AW;       // 2*CHUNK*128
    int tid = threadIdx.x;
    int ty = tid >> 4, tx = tid & 15;
    int n0 = blockIdx.x * 64;

    // A := h tile
    for (int idx = tid; idx < 64 * 32; idx += 128) {
        int i = idx >> 5, q = (idx & 31) * 4;
        int n = n0 + i;
        float4 v = make_float4(0.f, 0.f, 0.f, 0.f);
        if (n < Nn) v = *(const float4*)(h + (size_t)n * Hh + q);
        *(float4*)(sA + i * AW + q) = v;
    }

    unsigned long long acc2[8][4];
    gemm_tile<AW, true>(sA, sB, Wn1, Hh, ty, tx, tid, acc2);        // h @ Wn1_top

    // A := msg tile (trailing bar in gemm_tile makes this safe)
    for (int idx = tid; idx < 64 * 32; idx += 128) {
        int i = idx >> 5, q = (idx & 31) * 4;
        int n = n0 + i;
        float4 v = make_float4(0.f, 0.f, 0.f, 0.f);
        if (n < Nn) v = *(const float4*)(g_msg + (size_t)n * Hh + q);
        *(float4*)(sA + i * AW + q) = v;
    }
    gemm_tile<AW, false>(sA, sB, Wn1 + Hh * Hh, Hh, ty, tx, tid, acc2);  // += msg @ Wn1_bot

    bias_silu_store<AW>(acc2, bn1, sA, ty, tx);
    gemm_tile<AW, true>(sA, sB, Wn2, Hh, ty, tx, tid, acc2);

#pragma unroll
    for (int r = 0; r < 8; r++) {
        int n = n0 + ty * 8 + r;
        if (n < Nn) {
#pragma unroll
            for (int cp = 0; cp < 4; cp++) {
                U64F2 u; u.u = acc2[r][cp];
                int f = colof(tx, cp);
                float2 o;
                o.x = u.f.x + bn2[f]     + h[(size_t)n * Hh + f];
                o.y = u.f.y + bn2[f + 1] + h[(size_t)n * Hh + f + 1];
                *(float2*)(ho + (size_t)n * Hh + f) = o;
            }
        }
    }
}

// ---------------------------------------------------------------------------
static const int PRE_SMEM  = (64 * 132 + 2 * CHUNK * 128) * 4;                          // 50176
static const int EDGE_SMEM = (64 * 132 + 2 * CHUNK * 128 + 192 + 64 + 128 + 128) * 4;   // 52224
static const int NODE_SMEM = (64 * 132 + 2 * CHUNK * 128) * 4;                          // 50176

extern "C" void kernel_launch(void* const* d_in, const int* in_sizes, int n_in,
                              void* d_out, int out_size) {
    const float* h   = (const float*)d_in[0];
    const float* x   = (const float*)d_in[1];
    const int*   ei  = (const int*)d_in[2];
    const float* We1 = (const float*)d_in[3];
    const float* be1 = (const float*)d_in[4];
    const float* We2 = (const float*)d_in[5];
    const float* be2 = (const float*)d_in[6];
    const float* Wc1 = (const float*)d_in[7];
    const float* bc1 = (const float*)d_in[8];
    const float* Wc2 = (const float*)d_in[9];
    const float* Wn1 = (const float*)d_in[10];
    const float* bn1 = (const float*)d_in[11];
    const float* Wn2 = (const float*)d_in[12];
    const float* bn2 = (const float*)d_in[13];

    float* out = (float*)d_out;
    float* ho = out;                         // h_out: N*H
    float* xo = out + (size_t)Nn * Hh;       // x_out: N*3

    cudaFuncSetAttribute(pre_kernel,  cudaFuncAttributeMaxDynamicSharedMemorySize, PRE_SMEM);
    cudaFuncSetAttribute(edge_kernel, cudaFuncAttributeMaxDynamicSharedMemorySize, EDGE_SMEM);
    cudaFuncSetAttribute(node_kernel, cudaFuncAttributeMaxDynamicSharedMemorySize, NODE_SMEM);

    init_kernel<<<(Nn * Hh + 255) / 256, 256>>>(x, xo);
    pre_kernel<<<(Nn + 63) / 64, 128, PRE_SMEM>>>(h, We1, be1);
    edge_kernel<<<Ee / 64, 128, EDGE_SMEM>>>(x, ei, We1, We2, be2, Wc1, bc1, Wc2, xo);
    node_kernel<<<(Nn + 63) / 64, 128, NODE_SMEM>>>(h, Wn1, bn1, Wn2, bn2, ho);
}

// round 10
// speedup vs baseline: 1.2147x; 1.2147x over previous
#include <cuda_runtime.h>
#include <cuda_bf16.h>

#define Nn 50000
#define Ee 640000
#define Hh 128
#define CHUNK 16
#define NTILES 5000          // Ee / 128
#define EGRID 148

// ---------------- device-global scratch (no allocs allowed) ----------------
__device__ __align__(16) float g_msg[Nn * Hh];
__device__ __align__(16) float g_hs[Nn * Hh];   // h @ We1[0:128] + be1
__device__ __align__(16) float g_hd[Nn * Hh];   // h @ We1[128:256]
// B weights in mma.m16n8k16 fragment order, bf16 hi/lo split.
// img 0 = We2^T hi, 1 = We2^T lo, 2 = Wc1^T hi, 3 = Wc1^T lo
// layout: [img][kt*1024 + nt*64 + lane*2 + reg]  (uint32 = 2 bf16)
__device__ __align__(16) unsigned g_Bfrag[4][8192];

__device__ __forceinline__ float silu_f(float v) { return v / (1.f + __expf(-v)); }

union U64F2 { unsigned long long u; float2 f; };

// ---------------- cp.async ----------------
__device__ __forceinline__ void cp_async16(void* dst, const void* src) {
    unsigned u = (unsigned)__cvta_generic_to_shared(dst);
    asm volatile("cp.async.ca.shared.global [%0], [%1], 16;" :: "r"(u), "l"(src));
}
__device__ __forceinline__ void cp_commit() { asm volatile("cp.async.commit_group;"); }
template<int P> __device__ __forceinline__ void cp_wait() {
    asm volatile("cp.async.wait_group %0;" :: "n"(P));
}

// ---------------- warp mma (baseline sm_80+ PTX, compiles for sm_103) -------
__device__ __forceinline__ void mma_bf16(float* c, const unsigned* a,
                                         unsigned b0, unsigned b1) {
    asm volatile(
        "mma.sync.aligned.m16n8k16.row.col.f32.bf16.bf16.f32 "
        "{%0,%1,%2,%3}, {%4,%5,%6,%7}, {%8,%9}, {%0,%1,%2,%3};"
        : "+f"(c[0]), "+f"(c[1]), "+f"(c[2]), "+f"(c[3])
        : "r"(a[0]), "r"(a[1]), "r"(a[2]), "r"(a[3]), "r"(b0), "r"(b1));
}

__device__ __forceinline__ unsigned pack_bf2(float x, float y) {
    __nv_bfloat162 t = __floats2bfloat162_rn(x, y);
    return *(unsigned*)&t;
}
// split (x,y) into hi bf16 pair + lo residual bf16 pair
__device__ __forceinline__ void split2(float x, float y, unsigned& hi, unsigned& lo) {
    __nv_bfloat16 hx = __float2bfloat16(x), hy = __float2bfloat16(y);
    hi = (unsigned)__bfloat16_as_ushort(hx) | ((unsigned)__bfloat16_as_ushort(hy) << 16);
    lo = pack_bf2(x - __bfloat162float(hx), y - __bfloat162float(hy));
}

// ---------------------------------------------------------------------------
__global__ void init_kernel(const float* __restrict__ x, float* __restrict__ xo) {
    int idx = blockIdx.x * 256 + threadIdx.x;
    if (idx < Nn * 3) xo[idx] = x[idx];
    if (idx < Nn * Hh) g_msg[idx] = 0.f;
}

// prep: pack W^T (B col-major) into mma fragment order with bf16 hi/lo split.
// b-reg for (kt, nt, lane, reg): n = nt*8 + lane/4, k = kt*16 + reg*8 + (lane%4)*2
__global__ void prep_kernel(const float* __restrict__ We2, const float* __restrict__ Wc1) {
    int idx = blockIdx.x * 256 + threadIdx.x;
    if (idx >= 16384) return;
    int reg  = idx & 1;
    int lane = (idx >> 1) & 31;
    int nt   = (idx >> 6) & 15;
    int kt   = (idx >> 10) & 7;
    int mat  = idx >> 13;
    const float* W = mat ? Wc1 : We2;
    int n  = nt * 8 + (lane >> 2);
    int k0 = kt * 16 + reg * 8 + (lane & 3) * 2;
    float w0 = W[k0 * Hh + n];          // B[n][k] = W[k][n]
    float w1 = W[(k0 + 1) * Hh + n];
    unsigned hi, lo;
    split2(w0, w1, hi, lo);
    int off = kt * 1024 + nt * 64 + lane * 2 + reg;
    g_Bfrag[mat * 2 + 0][off] = hi;
    g_Bfrag[mat * 2 + 1][off] = lo;
}

// ---------------- SIMT gemm_tile (pre / node kernels) ----------------
__device__ __forceinline__ int colof(int tx, int cp) {
    return (cp < 2) ? (tx * 4 + cp * 2) : (64 + tx * 4 + (cp - 2) * 2);
}
__device__ __forceinline__ void stage_b(float* dst, const float* __restrict__ src, int tid) {
#pragma unroll
    for (int s = 0; s < CHUNK / 4; s++) {
        int idx = tid + s * 128;
        int row = idx >> 5, col = (idx & 31) * 4;
        cp_async16(dst + row * 128 + col, src + row * 128 + col);
    }
}
template <int AW, bool ZERO_INIT>
__device__ __forceinline__ void gemm_tile(
    const float* sA, float* sB, const float* __restrict__ Bg, int K,
    int ty, int tx, int tid, unsigned long long acc2[8][4])
{
    if (ZERO_INIT) {
#pragma unroll
        for (int r = 0; r < 8; r++)
#pragma unroll
            for (int cp = 0; cp < 4; cp++) acc2[r][cp] = 0ull;
    }
    const int nCh = K / CHUNK;
    stage_b(sB, Bg, tid);
    cp_commit();
    for (int c = 0; c < nCh; c++) {
        cp_wait<0>();
        __syncthreads();
        if (c + 1 < nCh) {
            stage_b(sB + ((c + 1) & 1) * (CHUNK * 128), Bg + (c + 1) * CHUNK * 128, tid);
            cp_commit();
        }
        const float* A  = sA + (ty * 8) * AW + c * CHUNK;
        const float* Bb = sB + (c & 1) * (CHUNK * 128);
#pragma unroll
        for (int kq = 0; kq < CHUNK / 4; kq++) {
            float4 a4[8];
#pragma unroll
            for (int r = 0; r < 8; r++)
                a4[r] = *(const float4*)(A + r * AW + kq * 4);
#pragma unroll
            for (int k2 = 0; k2 < 4; k2++) {
                const float* brow = Bb + (kq * 4 + k2) * 128;
                ulonglong2 t0 = *(const ulonglong2*)(brow + tx * 4);
                ulonglong2 t1 = *(const ulonglong2*)(brow + 64 + tx * 4);
                unsigned long long b2[4] = { t0.x, t0.y, t1.x, t1.y };
#pragma unroll
                for (int r = 0; r < 8; r++) {
                    float a = (k2 == 0) ? a4[r].x : (k2 == 1) ? a4[r].y
                             : (k2 == 2) ? a4[r].z : a4[r].w;
                    unsigned long long a2;
                    asm("mov.b64 %0, {%1, %1};" : "=l"(a2) : "f"(a));
#pragma unroll
                    for (int cp = 0; cp < 4; cp++)
                        asm("fma.rn.f32x2 %0, %1, %2, %0;"
                            : "+l"(acc2[r][cp]) : "l"(a2), "l"(b2[cp]));
                }
            }
        }
    }
    __syncthreads();
}
template <int AW>
__device__ __forceinline__ void bias_silu_store(
    unsigned long long acc2[8][4], const float* __restrict__ bias,
    float* sA, int ty, int tx)
{
#pragma unroll
    for (int r = 0; r < 8; r++) {
        float* row = sA + (ty * 8 + r) * AW;
        U64F2 u0, u1;
        u0.u = acc2[r][0]; u1.u = acc2[r][1];
        float4 v0;
        v0.x = silu_f(u0.f.x + bias[tx * 4 + 0]);
        v0.y = silu_f(u0.f.y + bias[tx * 4 + 1]);
        v0.z = silu_f(u1.f.x + bias[tx * 4 + 2]);
        v0.w = silu_f(u1.f.y + bias[tx * 4 + 3]);
        *(float4*)(row + tx * 4) = v0;
        u0.u = acc2[r][2]; u1.u = acc2[r][3];
        float4 v1;
        v1.x = silu_f(u0.f.x + bias[64 + tx * 4 + 0]);
        v1.y = silu_f(u0.f.y + bias[64 + tx * 4 + 1]);
        v1.z = silu_f(u1.f.x + bias[64 + tx * 4 + 2]);
        v1.w = silu_f(u1.f.y + bias[64 + tx * 4 + 3]);
        *(float4*)(row + 64 + tx * 4) = v1;
    }
}

// ---------------------------------------------------------------------------
// precompute: g_hs = h @ We1[0:128] + be1 ; g_hd = h @ We1[128:256]
__global__ __launch_bounds__(128, 3) void pre_kernel(
    const float* __restrict__ h, const float* __restrict__ We1,
    const float* __restrict__ be1)
{
    const int AW = 132;
    extern __shared__ float sm[];
    float* sA = sm;
    float* sB = sm + 64 * AW;
    int tid = threadIdx.x;
    int ty = tid >> 4, tx = tid & 15;
    int n0 = blockIdx.x * 64;

    for (int idx = tid; idx < 64 * 32; idx += 128) {
        int i = idx >> 5, q = (idx & 31) * 4;
        int n = n0 + i;
        float4 v = make_float4(0.f, 0.f, 0.f, 0.f);
        if (n < Nn) v = *(const float4*)(h + (size_t)n * Hh + q);
        *(float4*)(sA + i * AW + q) = v;
    }

    unsigned long long acc2[8][4];
    gemm_tile<AW, true>(sA, sB, We1, Hh, ty, tx, tid, acc2);
#pragma unroll
    for (int r = 0; r < 8; r++) {
        int n = n0 + ty * 8 + r;
        if (n < Nn) {
#pragma unroll
            for (int cp = 0; cp < 4; cp++) {
                U64F2 u; u.u = acc2[r][cp];
                int f = colof(tx, cp);
                float2 o; o.x = u.f.x + be1[f]; o.y = u.f.y + be1[f + 1];
                *(float2*)(g_hs + (size_t)n * Hh + f) = o;
            }
        }
    }
    gemm_tile<AW, true>(sA, sB, We1 + 128 * Hh, Hh, ty, tx, tid, acc2);
#pragma unroll
    for (int r = 0; r < 8; r++) {
        int n = n0 + ty * 8 + r;
        if (n < Nn) {
#pragma unroll
            for (int cp = 0; cp < 4; cp++) {
                U64F2 u; u.u = acc2[r][cp];
                *(float2*)(g_hd + (size_t)n * Hh + colof(tx, cp)) = u.f;
            }
        }
    }
}

// ---------------------------------------------------------------------------
// tensor edge kernel (mma.sync bf16 split): persistent, 256 thr, 128 edges/tile.
// smem: B fragments 128 KB + per-tile metadata + small consts.
#define SB_U32   8192                      // uints per image
#define SM_META  (4 * SB_U32)              // uint offset of metadata block
// metadata floats (after 32768 uints): rel[384], d2[128], w256[128], be2[128],
// bc1[128], wc2[128]; ints src[128], dst[128]
__global__ __launch_bounds__(256) void edge_kernel_mma(
    const float* __restrict__ x, const int* __restrict__ ei,
    const float* __restrict__ We1,
    const float* __restrict__ be2, const float* __restrict__ bc1,
    const float* __restrict__ Wc2, float* __restrict__ xo)
{
    extern __shared__ unsigned su[];
    float* sRel  = (float*)(su + SM_META);
    float* sD2   = sRel + 384;
    float* sW256 = sD2 + 128;
    float* sBe2  = sW256 + 128;
    float* sBc1  = sBe2 + 128;
    float* sWc2  = sBc1 + 128;
    int*   sSrc  = (int*)(sWc2 + 128);
    int*   sDst  = sSrc + 128;

    const int tid  = threadIdx.x;
    const int wid  = tid >> 5;
    const int lane = tid & 31;
    const int g    = lane >> 2;      // row group
    const int t4   = lane & 3;

    // one-time: stage all 4 B images (128 KB) + constants
    for (int i = tid; i < 4 * SB_U32 / 4; i += 256)
        cp_async16(su + i * 4, (const unsigned*)g_Bfrag + i * 4);
    cp_commit();
    if (tid < 128) {
        sW256[tid] = We1[256 * Hh + tid];
        sBe2[tid]  = be2[tid];
        sBc1[tid]  = bc1[tid];
        sWc2[tid]  = Wc2[tid];
    }
    cp_wait<0>();
    __syncthreads();

    const int r0l = wid * 16 + g;          // this thread's two tile-rows
    const int r1l = r0l + 8;

    for (int tile = blockIdx.x; tile < NTILES; tile += EGRID) {
        __syncthreads();                   // prior tile's metadata readers done
        if (tid < 128) {
            int ge = tile * 128 + tid;
            int s = ei[ge], d = ei[Ee + ge];
            float rx = x[s * 3 + 0] - x[d * 3 + 0];
            float ry = x[s * 3 + 1] - x[d * 3 + 1];
            float rz = x[s * 3 + 2] - x[d * 3 + 2];
            sRel[tid * 3 + 0] = rx; sRel[tid * 3 + 1] = ry; sRel[tid * 3 + 2] = rz;
            sD2[tid] = rx * rx + ry * ry + rz * rz;
            sSrc[tid] = s; sDst[tid] = d;
        }
        __syncthreads();

        const int s0 = sSrc[r0l], d0 = sDst[r0l];
        const int s1 = sSrc[r1l], d1 = sDst[r1l];
        const float d2_0 = sD2[r0l], d2_1 = sD2[r1l];

        // ---- layer-1 gather directly into A fragments (hi/lo) ----
        unsigned aHi[8][4], aLo[8][4];
#pragma unroll
        for (int kt = 0; kt < 8; kt++) {
            int k0 = kt * 16 + 2 * t4;
            float2 wA = *(const float2*)(sW256 + k0);
            float2 wB = *(const float2*)(sW256 + k0 + 8);
            float2 hsA, hdA, hsB, hdB;
            // row 0
            hsA = *(const float2*)(g_hs + (size_t)s0 * Hh + k0);
            hdA = *(const float2*)(g_hd + (size_t)d0 * Hh + k0);
            hsB = *(const float2*)(g_hs + (size_t)s0 * Hh + k0 + 8);
            hdB = *(const float2*)(g_hd + (size_t)d0 * Hh + k0 + 8);
            split2(silu_f(hsA.x + hdA.x + d2_0 * wA.x),
                   silu_f(hsA.y + hdA.y + d2_0 * wA.y), aHi[kt][0], aLo[kt][0]);
            split2(silu_f(hsB.x + hdB.x + d2_0 * wB.x),
                   silu_f(hsB.y + hdB.y + d2_0 * wB.y), aHi[kt][2], aLo[kt][2]);
            // row 1
            hsA = *(const float2*)(g_hs + (size_t)s1 * Hh + k0);
            hdA = *(const float2*)(g_hd + (size_t)d1 * Hh + k0);
            hsB = *(const float2*)(g_hs + (size_t)s1 * Hh + k0 + 8);
            hdB = *(const float2*)(g_hd + (size_t)d1 * Hh + k0 + 8);
            split2(silu_f(hsA.x + hdA.x + d2_1 * wA.x),
                   silu_f(hsA.y + hdA.y + d2_1 * wA.y), aHi[kt][1], aLo[kt][1]);
            split2(silu_f(hsB.x + hdB.x + d2_1 * wB.x),
                   silu_f(hsB.y + hdB.y + d2_1 * wB.y), aHi[kt][3], aLo[kt][3]);
        }

        // ---- GEMM1: C = A @ We2^T  (3-pass split) ----
        float acc[16][4];
#pragma unroll
        for (int nt = 0; nt < 16; nt++)
#pragma unroll
            for (int j = 0; j < 4; j++) acc[nt][j] = 0.f;
#pragma unroll
        for (int kt = 0; kt < 8; kt++) {
            const unsigned* bh = su + 0 * SB_U32 + kt * 1024 + lane * 2;
            const unsigned* bl = su + 1 * SB_U32 + kt * 1024 + lane * 2;
#pragma unroll
            for (int nt = 0; nt < 16; nt++) {
                uint2 bH = *(const uint2*)(bh + nt * 64);
                uint2 bL = *(const uint2*)(bl + nt * 64);
                mma_bf16(acc[nt], aHi[kt], bH.x, bH.y);
                mma_bf16(acc[nt], aHi[kt], bL.x, bL.y);
                mma_bf16(acc[nt], aLo[kt], bH.x, bH.y);
            }
        }

        // ---- epilogue 1: m = silu(C + be2); scatter; re-pack as A fragments ----
        float* msg0 = g_msg + (size_t)d0 * Hh;
        float* msg1 = g_msg + (size_t)d1 * Hh;
#pragma unroll
        for (int kt = 0; kt < 8; kt++) {
            int c = kt * 16 + 2 * t4;
            float m00 = silu_f(acc[2 * kt][0]     + sBe2[c]);
            float m01 = silu_f(acc[2 * kt][1]     + sBe2[c + 1]);
            float m10 = silu_f(acc[2 * kt][2]     + sBe2[c]);
            float m11 = silu_f(acc[2 * kt][3]     + sBe2[c + 1]);
            float m02 = silu_f(acc[2 * kt + 1][0] + sBe2[c + 8]);
            float m03 = silu_f(acc[2 * kt + 1][1] + sBe2[c + 9]);
            float m12 = silu_f(acc[2 * kt + 1][2] + sBe2[c + 8]);
            float m13 = silu_f(acc[2 * kt + 1][3] + sBe2[c + 9]);
            asm volatile("red.global.add.v2.f32 [%0], {%1, %2};"
                         :: "l"(msg0 + c),     "f"(m00), "f"(m01) : "memory");
            asm volatile("red.global.add.v2.f32 [%0], {%1, %2};"
                         :: "l"(msg0 + c + 8), "f"(m02), "f"(m03) : "memory");
            asm volatile("red.global.add.v2.f32 [%0], {%1, %2};"
                         :: "l"(msg1 + c),     "f"(m10), "f"(m11) : "memory");
            asm volatile("red.global.add.v2.f32 [%0], {%1, %2};"
                         :: "l"(msg1 + c + 8), "f"(m12), "f"(m13) : "memory");
            split2(m00, m01, aHi[kt][0], aLo[kt][0]);
            split2(m10, m11, aHi[kt][1], aLo[kt][1]);
            split2(m02, m03, aHi[kt][2], aLo[kt][2]);
            split2(m12, m13, aHi[kt][3], aLo[kt][3]);
        }

        // ---- GEMM2: C = M @ Wc1^T ----
#pragma unroll
        for (int nt = 0; nt < 16; nt++)
#pragma unroll
            for (int j = 0; j < 4; j++) acc[nt][j] = 0.f;
#pragma unroll
        for (int kt = 0; kt < 8; kt++) {
            const unsigned* bh = su + 2 * SB_U32 + kt * 1024 + lane * 2;
            const unsigned* bl = su + 3 * SB_U32 + kt * 1024 + lane * 2;
#pragma unroll
            for (int nt = 0; nt < 16; nt++) {
                uint2 bH = *(const uint2*)(bh + nt * 64);
                uint2 bL = *(const uint2*)(bl + nt * 64);
                mma_bf16(acc[nt], aHi[kt], bH.x, bH.y);
                mma_bf16(acc[nt], aHi[kt], bL.x, bL.y);
                mma_bf16(acc[nt], aLo[kt], bH.x, bH.y);
            }
        }

        // ---- epilogue 2: per-edge coord weight + atomic scatter ----
        float ws0 = 0.f, ws1 = 0.f;
#pragma unroll
        for (int nt = 0; nt < 16; nt++) {
            int c = nt * 8 + 2 * t4;
            ws0 += silu_f(acc[nt][0] + sBc1[c])     * sWc2[c];
            ws0 += silu_f(acc[nt][1] + sBc1[c + 1]) * sWc2[c + 1];
            ws1 += silu_f(acc[nt][2] + sBc1[c])     * sWc2[c];
            ws1 += silu_f(acc[nt][3] + sBc1[c + 1]) * sWc2[c + 1];
        }
        ws0 += __shfl_xor_sync(0xffffffffu, ws0, 1);
        ws0 += __shfl_xor_sync(0xffffffffu, ws0, 2);
        ws1 += __shfl_xor_sync(0xffffffffu, ws1, 1);
        ws1 += __shfl_xor_sync(0xffffffffu, ws1, 2);
        if (t4 == 0) {
            atomicAdd(xo + (size_t)d0 * 3 + 0, sRel[r0l * 3 + 0] * ws0);
            atomicAdd(xo + (size_t)d0 * 3 + 1, sRel[r0l * 3 + 1] * ws0);
            atomicAdd(xo + (size_t)d0 * 3 + 2, sRel[r0l * 3 + 2] * ws0);
            atomicAdd(xo + (size_t)d1 * 3 + 0, sRel[r1l * 3 + 0] * ws1);
            atomicAdd(xo + (size_t)d1 * 3 + 1, sRel[r1l * 3 + 1] * ws1);
            atomicAdd(xo + (size_t)d1 * 3 + 2, sRel[r1l * 3 + 2] * ws1);
        }
    }
}

// ---------------------------------------------------------------------------
// node kernel: h_out = h + Wn2 @ SiLU(h@Wn1_top + msg@Wn1_bot + bn1) + bn2
__global__ __launch_bounds__(128, 3) void node_kernel(
    const float* __restrict__ h,
    const float* __restrict__ Wn1, const float* __restrict__ bn1,
    const float* __restrict__ Wn2, const float* __restrict__ bn2,
    float* __restrict__ ho)
{
    const int AW = 132;
    extern __shared__ float sm[];
    float* sA = sm;
    float* sB = sm + 64 * AW;
    int tid = threadIdx.x;
    int ty = tid >> 4, tx = tid & 15;
    int n0 = blockIdx.x * 64;

    for (int idx = tid; idx < 64 * 32; idx += 128) {
        int i = idx >> 5, q = (idx & 31) * 4;
        int n = n0 + i;
        float4 v = make_float4(0.f, 0.f, 0.f, 0.f);
        if (n < Nn) v = *(const float4*)(h + (size_t)n * Hh + q);
        *(float4*)(sA + i * AW + q) = v;
    }

    unsigned long long acc2[8][4];
    gemm_tile<AW, true>(sA, sB, Wn1, Hh, ty, tx, tid, acc2);

    for (int idx = tid; idx < 64 * 32; idx += 128) {
        int i = idx >> 5, q = (idx & 31) * 4;
        int n = n0 + i;
        float4 v = make_float4(0.f, 0.f, 0.f, 0.f);
        if (n < Nn) v = *(const float4*)(g_msg + (size_t)n * Hh + q);
        *(float4*)(sA + i * AW + q) = v;
    }
    gemm_tile<AW, false>(sA, sB, Wn1 + Hh * Hh, Hh, ty, tx, tid, acc2);

    bias_silu_store<AW>(acc2, bn1, sA, ty, tx);
    gemm_tile<AW, true>(sA, sB, Wn2, Hh, ty, tx, tid, acc2);

#pragma unroll
    for (int r = 0; r < 8; r++) {
        int n = n0 + ty * 8 + r;
        if (n < Nn) {
#pragma unroll
            for (int cp = 0; cp < 4; cp++) {
                U64F2 u; u.u = acc2[r][cp];
                int f = colof(tx, cp);
                float2 o;
                o.x = u.f.x + bn2[f]     + h[(size_t)n * Hh + f];
                o.y = u.f.y + bn2[f + 1] + h[(size_t)n * Hh + f + 1];
                *(float2*)(ho + (size_t)n * Hh + f) = o;
            }
        }
    }
}

// ---------------------------------------------------------------------------
static const int PRE_SMEM  = (64 * 132 + 2 * CHUNK * 128) * 4;
static const int NODE_SMEM = (64 * 132 + 2 * CHUNK * 128) * 4;
static const int EDGE_SMEM_M = 4 * 8192 * 4      // B fragments (131072)
                             + (384 + 128 * 5) * 4   // rel/d2/w256/be2/bc1/wc2
                             + 256 * 4;              // src/dst

extern "C" void kernel_launch(void* const* d_in, const int* in_sizes, int n_in,
                              void* d_out, int out_size) {
    const float* h   = (const float*)d_in[0];
    const float* x   = (const float*)d_in[1];
    const int*   ei  = (const int*)d_in[2];
    const float* We1 = (const float*)d_in[3];
    const float* be1 = (const float*)d_in[4];
    const float* We2 = (const float*)d_in[5];
    const float* be2 = (const float*)d_in[6];
    const float* Wc1 = (const float*)d_in[7];
    const float* bc1 = (const float*)d_in[8];
    const float* Wc2 = (const float*)d_in[9];
    const float* Wn1 = (const float*)d_in[10];
    const float* bn1 = (const float*)d_in[11];
    const float* Wn2 = (const float*)d_in[12];
    const float* bn2 = (const float*)d_in[13];

    float* out = (float*)d_out;
    float* ho = out;                         // h_out: N*H
    float* xo = out + (size_t)Nn * Hh;       // x_out: N*3

    cudaFuncSetAttribute(pre_kernel,  cudaFuncAttributeMaxDynamicSharedMemorySize, PRE_SMEM);
    cudaFuncSetAttribute(edge_kernel_mma, cudaFuncAttributeMaxDynamicSharedMemorySize, EDGE_SMEM_M);
    cudaFuncSetAttribute(node_kernel, cudaFuncAttributeMaxDynamicSharedMemorySize, NODE_SMEM);

    init_kernel<<<(Nn * Hh + 255) / 256, 256>>>(x, xo);
    prep_kernel<<<64, 256>>>(We2, Wc1);
    pre_kernel<<<(Nn + 63) / 64, 128, PRE_SMEM>>>(h, We1, be1);
    edge_kernel_mma<<<EGRID, 256, EDGE_SMEM_M>>>(x, ei, We1, be2, bc1, Wc2, xo);
    node_kernel<<<(Nn + 63) / 64, 128, NODE_SMEM>>>(h, Wn1, bn1, Wn2, bn2, ho);
}